// round 1
// baseline (speedup 1.0000x reference)
#include <cuda_runtime.h>
#include <math.h>

#define TT   4096
#define HH   1024
#define EE   8
#define KSEL 2
#define DFF  4096

// ---------------- scratch (static device globals; no allocation) ----------------
__device__ float g_h[TT * HH];              // backbone activations h            (16 MB)
__device__ float g_mid[TT * KSEL * DFF];    // FFN intermediate (reused)         (134 MB)
__device__ float g_out[TT * HH];            // combined output before head       (16 MB)
__device__ int   g_idx[EE * TT];            // token index per (expert, slot)
__device__ float g_w[EE * TT];              // combine weight per (expert, slot) (= topw * coef0)
__device__ float g_c1[TT];                  // residual mixing coefficient
__device__ int   g_cnt[EE];
__device__ int   g_off[EE];
__device__ float g_me[EE];                  // sum of gate probs per expert
__device__ float g_ce[EE];                  // count of top-1 assignments per expert

// ---------------- tiny kernels ----------------
__global__ void zero_small() {
    int i = threadIdx.x;
    if (i < EE) { g_cnt[i] = 0; g_me[i] = 0.f; g_ce[i] = 0.f; }
}

__global__ void offsets_kernel() {
    if (threadIdx.x == 0) {
        int o = 0;
        for (int e = 0; e < EE; e++) { g_off[e] = o; o += g_cnt[e]; }
    }
}

__global__ void laux_kernel(float* out, int pos) {
    if (threadIdx.x == 0) {
        float la = 0.f;
        for (int e = 0; e < EE; e++)
            la += (g_me[e] / (float)TT) * (g_ce[e] / (float)TT) * (float)EE;
        out[pos] = la;
    }
}

// ---------------- gating: softmax over 8 experts, top-2, coef, stats ----------------
__global__ void gating_kernel(const float* __restrict__ Wg,
                              const float* __restrict__ Wc,
                              const float* __restrict__ bc) {
    int t = blockIdx.x;
    const float* hr = g_h + (size_t)t * HH;
    float accg[8] = {0.f,0.f,0.f,0.f,0.f,0.f,0.f,0.f};
    float c0a = 0.f, c1a = 0.f;
    for (int k = threadIdx.x; k < HH; k += 128) {
        float xv = hr[k];
        const float* wg = Wg + k * EE;
        #pragma unroll
        for (int e = 0; e < 8; e++) accg[e] += xv * wg[e];
        c0a += xv * Wc[k * 2 + 0];
        c1a += xv * Wc[k * 2 + 1];
    }
    __shared__ float red[128];
    __shared__ float vals[10];
    for (int v = 0; v < 10; v++) {
        float xx = (v < 8) ? accg[v] : ((v == 8) ? c0a : c1a);
        red[threadIdx.x] = xx; __syncthreads();
        for (int s = 64; s > 0; s >>= 1) {
            if (threadIdx.x < s) red[threadIdx.x] += red[threadIdx.x + s];
            __syncthreads();
        }
        if (threadIdx.x == 0) vals[v] = red[0];
        __syncthreads();
    }
    if (threadIdx.x == 0) {
        float g[8], mx = -1e30f;
        #pragma unroll
        for (int e = 0; e < 8; e++) mx = fmaxf(mx, vals[e]);
        float s = 0.f;
        #pragma unroll
        for (int e = 0; e < 8; e++) { g[e] = expf(vals[e] - mx); s += g[e]; }
        float invs = 1.f / s;
        #pragma unroll
        for (int e = 0; e < 8; e++) g[e] *= invs;
        // top-2 (ties -> lower index, matching lax.top_k)
        int i1 = 0;
        #pragma unroll
        for (int e = 1; e < 8; e++) if (g[e] > g[i1]) i1 = e;
        int i2 = (i1 == 0) ? 1 : 0;
        #pragma unroll
        for (int e = 0; e < 8; e++) if (e != i1 && g[e] > g[i2]) i2 = e;
        float v1 = g[i1], v2 = g[i2];
        float wn = 1.f / (v1 + v2 + 1e-9f);
        // mixing coef = softmax2(h@Wc + bc)
        float cc0 = vals[8] + bc[0], cc1 = vals[9] + bc[1];
        float m2 = fmaxf(cc0, cc1);
        float e0 = expf(cc0 - m2), e1 = expf(cc1 - m2);
        float cs = 1.f / (e0 + e1);
        float c0 = e0 * cs, c1 = e1 * cs;
        g_c1[t] = c1;
        int s1 = atomicAdd(&g_cnt[i1], 1);
        g_idx[i1 * TT + s1] = t; g_w[i1 * TT + s1] = v1 * wn * c0;
        int s2 = atomicAdd(&g_cnt[i2], 1);
        g_idx[i2 * TT + s2] = t; g_w[i2 * TT + s2] = v2 * wn * c0;
        #pragma unroll
        for (int e = 0; e < 8; e++) atomicAdd(&g_me[e], g[e]);
        atomicAdd(&g_ce[i1], 1.0f);
    }
}

// ---------------- tiled fp32 GEMM, 128x128x16 block tile, 8x8 per thread ----------------
// MODE 0: C[r] = relu(acc + bias[n])                       (dense A)
// MODE 1: C[r] = (acc + bias[n]) * rowscale[r]             (dense A)      [residual out]
// MODE 2: gathered A rows via g_idx; C row at g_off[e]+r; relu(acc+bias_e) [expert FFN-1]
// MODE 3: A rows at g_off[e]+r; atomicAdd(C[t], w*(acc+bias_e))            [expert FFN-2]
template <int MODE>
__global__ __launch_bounds__(256)
void gemm_k(const float* __restrict__ A, const float* __restrict__ B,
            float* __restrict__ C, const float* __restrict__ bias,
            int M, int N, int Kd, const float* __restrict__ rowscale) {
    const int e = blockIdx.z;
    int Mloc = M;
    if (MODE == 2 || MODE == 3) Mloc = g_cnt[e];
    const int m0 = blockIdx.y * 128;
    if (m0 >= Mloc) return;
    const int n0 = blockIdx.x * 128;
    const float* Bp = B + (size_t)e * Kd * N;
    const float* bp = bias + (size_t)e * N;
    const int tid = threadIdx.x;

    __shared__ float As[16][128];
    __shared__ float Bs[16][128];

    // A loader mapping: each thread loads 8 consecutive k for one row
    const int la_r = tid >> 1;
    const int la_k = (tid & 1) * 8;
    const int arow = m0 + la_r;
    const bool aval = arow < Mloc;
    const float* aptr;
    if (MODE == 2) {
        int trow = aval ? g_idx[e * TT + arow] : 0;
        aptr = A + (size_t)trow * Kd;
    } else if (MODE == 3) {
        aptr = A + (size_t)(g_off[e] + (aval ? arow : 0)) * Kd;
    } else {
        aptr = A + (size_t)(aval ? arow : 0) * Kd;
    }

    const int lb_k = tid >> 4;
    const int lb_n = (tid & 15) * 8;
    const int ty = tid >> 4, tx = tid & 15;

    float acc[8][8];
    #pragma unroll
    for (int i = 0; i < 8; i++)
        #pragma unroll
        for (int j = 0; j < 8; j++) acc[i][j] = 0.f;

    for (int k0 = 0; k0 < Kd; k0 += 16) {
        float4 av0, av1;
        if (aval) {
            av0 = *reinterpret_cast<const float4*>(aptr + k0 + la_k);
            av1 = *reinterpret_cast<const float4*>(aptr + k0 + la_k + 4);
        } else {
            av0 = make_float4(0.f, 0.f, 0.f, 0.f); av1 = av0;
        }
        As[la_k + 0][la_r] = av0.x; As[la_k + 1][la_r] = av0.y;
        As[la_k + 2][la_r] = av0.z; As[la_k + 3][la_r] = av0.w;
        As[la_k + 4][la_r] = av1.x; As[la_k + 5][la_r] = av1.y;
        As[la_k + 6][la_r] = av1.z; As[la_k + 7][la_r] = av1.w;

        const float* bptr = Bp + (size_t)(k0 + lb_k) * N + n0 + lb_n;
        float4 bv0 = *reinterpret_cast<const float4*>(bptr);
        float4 bv1 = *reinterpret_cast<const float4*>(bptr + 4);
        *reinterpret_cast<float4*>(&Bs[lb_k][lb_n]) = bv0;
        *reinterpret_cast<float4*>(&Bs[lb_k][lb_n + 4]) = bv1;
        __syncthreads();

        #pragma unroll
        for (int k = 0; k < 16; k++) {
            float a[8], b[8];
            #pragma unroll
            for (int i = 0; i < 8; i++) a[i] = As[k][ty * 8 + i];
            #pragma unroll
            for (int j = 0; j < 8; j++) b[j] = Bs[k][tx * 8 + j];
            #pragma unroll
            for (int i = 0; i < 8; i++)
                #pragma unroll
                for (int j = 0; j < 8; j++) acc[i][j] += a[i] * b[j];
        }
        __syncthreads();
    }

    #pragma unroll
    for (int i = 0; i < 8; i++) {
        int r = m0 + ty * 8 + i;
        if (r >= Mloc) break;
        if (MODE == 0) {
            float* crow = C + (size_t)r * N + n0 + tx * 8;
            #pragma unroll
            for (int j = 0; j < 8; j++)
                crow[j] = fmaxf(acc[i][j] + bp[n0 + tx * 8 + j], 0.f);
        } else if (MODE == 1) {
            float sc = rowscale[r];
            float* crow = C + (size_t)r * N + n0 + tx * 8;
            #pragma unroll
            for (int j = 0; j < 8; j++)
                crow[j] = (acc[i][j] + bp[n0 + tx * 8 + j]) * sc;
        } else if (MODE == 2) {
            float* crow = C + (size_t)(g_off[e] + r) * N + n0 + tx * 8;
            #pragma unroll
            for (int j = 0; j < 8; j++)
                crow[j] = fmaxf(acc[i][j] + bp[n0 + tx * 8 + j], 0.f);
        } else {
            int tt = g_idx[e * TT + r];
            float wv = g_w[e * TT + r];
            float* crow = C + (size_t)tt * N + n0 + tx * 8;
            #pragma unroll
            for (int j = 0; j < 8; j++)
                atomicAdd(&crow[j], wv * (acc[i][j] + bp[n0 + tx * 8 + j]));
        }
    }
}

// ---------------- head: logits = g_out @ Wh + bh (warp per token) ----------------
__global__ void head_kernel(const float* __restrict__ Wh,
                            const float* __restrict__ bh,
                            float* __restrict__ logits) {
    __shared__ float sWt[10 * 1024];  // transposed: [c][k] for conflict-free reads
    for (int i = threadIdx.x; i < 10240; i += 256) {
        int k = i / 10, c = i % 10;
        sWt[c * 1024 + k] = Wh[i];
    }
    __syncthreads();
    int warp = threadIdx.x >> 5, lane = threadIdx.x & 31;
    int t = blockIdx.x * 8 + warp;
    const float* orow = g_out + (size_t)t * HH;
    float acc[10];
    #pragma unroll
    for (int c = 0; c < 10; c++) acc[c] = 0.f;
    for (int k = lane; k < HH; k += 32) {
        float xv = orow[k];
        #pragma unroll
        for (int c = 0; c < 10; c++) acc[c] += xv * sWt[c * 1024 + k];
    }
    #pragma unroll
    for (int c = 0; c < 10; c++) {
        #pragma unroll
        for (int s = 16; s > 0; s >>= 1)
            acc[c] += __shfl_down_sync(0xffffffffu, acc[c], s);
    }
    if (lane == 0) {
        #pragma unroll
        for (int c = 0; c < 10; c++) logits[t * 10 + c] = acc[c] + bh[c];
    }
}

// ---------------- launch ----------------
extern "C" void kernel_launch(void* const* d_in, const int* in_sizes, int n_in,
                              void* d_out, int out_size) {
    const float* x   = (const float*)d_in[0];
    const float* Wb  = (const float*)d_in[1];
    const float* bb  = (const float*)d_in[2];
    const float* Wg  = (const float*)d_in[3];
    const float* W1  = (const float*)d_in[4];
    const float* b1  = (const float*)d_in[5];
    const float* W2  = (const float*)d_in[6];
    const float* b2  = (const float*)d_in[7];
    const float* Wr1 = (const float*)d_in[8];
    const float* br1 = (const float*)d_in[9];
    const float* Wr2 = (const float*)d_in[10];
    const float* br2 = (const float*)d_in[11];
    const float* Wc  = (const float*)d_in[12];
    const float* bc  = (const float*)d_in[13];
    const float* Wh  = (const float*)d_in[14];
    const float* bh  = (const float*)d_in[15];
    float* out = (float*)d_out;

    float *ph, *pmid, *pout, *pc1;
    cudaGetSymbolAddress((void**)&ph,   g_h);
    cudaGetSymbolAddress((void**)&pmid, g_mid);
    cudaGetSymbolAddress((void**)&pout, g_out);
    cudaGetSymbolAddress((void**)&pc1,  g_c1);

    zero_small<<<1, 32>>>();

    // backbone: h = relu(x @ Wb + bb)
    gemm_k<0><<<dim3(HH / 128, TT / 128, 1), 256>>>(x, Wb, ph, bb, TT, HH, HH, nullptr);

    // gating + aux-loss stats + routing lists
    gating_kernel<<<TT, 128>>>(Wg, Wc, bc);
    offsets_kernel<<<1, 32>>>();
    laux_kernel<<<1, 32>>>(out, out_size - 1);

    // residual branch: g_out = (relu(h@Wr1+br1) @ Wr2 + br2) * coef1
    gemm_k<0><<<dim3(DFF / 128, TT / 128, 1), 256>>>(ph, Wr1, pmid, br1, TT, DFF, HH, nullptr);
    gemm_k<1><<<dim3(HH / 128, TT / 128, 1), 256>>>(pmid, Wr2, pout, br2, TT, HH, DFF, pc1);

    // expert branch (sparse, grouped): g_out += sum_k w_k*coef0 * FFN_e(h)
    gemm_k<2><<<dim3(DFF / 128, TT / 128, EE), 256>>>(ph, W1, pmid, b1, TT, DFF, HH, nullptr);
    gemm_k<3><<<dim3(HH / 128, TT / 128, EE), 256>>>(pmid, W2, pout, b2, TT, HH, DFF, nullptr);

    // head
    head_kernel<<<TT / 8, 256>>>(Wh, bh, out);
}

// round 4
// speedup vs baseline: 2.0877x; 2.0877x over previous
#include <cuda_runtime.h>
#include <cuda_bf16.h>
#include <math.h>
#include <stdint.h>

#define TT   4096
#define HH   1024
#define EE   8
#define DFF  4096

typedef __nv_bfloat16 bf16;

// ---------------- scratch (static device globals; no allocation) ----------------
__device__ float g_h[TT * HH];                 // fp32 backbone activations (gating)
__device__ bf16  g_hh[TT * HH];                // h split hi
__device__ bf16  g_hl[TT * HH];                // h split lo
__device__ bf16  g_xh[TT * HH];
__device__ bf16  g_xl[TT * HH];
__device__ bf16  g_mh[3 * TT * DFF];           // mid hi: rows [0,TT) resid, [TT,3TT) expert-packed
__device__ bf16  g_ml[3 * TT * DFF];           // mid lo
__device__ float g_out[TT * HH];
__device__ int   g_idx[EE * TT];
__device__ float g_w[EE * TT];
__device__ float g_c1[TT];
__device__ int   g_cnt[EE];
__device__ int   g_off[EE];
__device__ float g_me[EE];
__device__ float g_ce[EE];

// transposed+split weight arenas: [N,K] K-major bf16
#define OFF_WB   0
#define OFF_WR1  (1024 * 1024)
#define OFF_WR2  (OFF_WR1 + 1024 * 4096)
#define OFF_W1   (OFF_WR2 + 4096 * 1024)
#define OFF_W2   (OFF_W1 + 8 * 1024 * 4096)
#define WT_TOTAL (OFF_W2 + 8 * 4096 * 1024)
__device__ bf16 g_Wh[WT_TOTAL];
__device__ bf16 g_Wl[WT_TOTAL];

// ---------------- PTX helpers (sm_80-baseline only; NO 'a'-features) ----------------
__device__ __forceinline__ uint32_t s2u(const void* p) {
    uint32_t a;
    asm("{ .reg .u64 t; cvta.to.shared.u64 t, %1; cvt.u32.u64 %0, t; }" : "=r"(a) : "l"(p));
    return a;
}
__device__ __forceinline__ void cpa16(uint32_t s, const void* g, bool v) {
    asm volatile("cp.async.cg.shared.global [%0], [%1], 16, %2;"
                 :: "r"(s), "l"(g), "r"(v ? 16 : 0));
}
#define CPCOMMIT() asm volatile("cp.async.commit_group;")
#define CPWAIT(n)  asm volatile("cp.async.wait_group %0;" :: "n"(n))

#define LDSM4(r, a) \
    asm volatile("ldmatrix.sync.aligned.m8n8.x4.shared.b16 {%0,%1,%2,%3}, [%4];" \
        : "=r"((r)[0]), "=r"((r)[1]), "=r"((r)[2]), "=r"((r)[3]) : "r"(a))
// B stored [N,K] K-major: NON-trans x2 yields exactly the mma col-major B fragment
#define LDSM2(r, a) \
    asm volatile("ldmatrix.sync.aligned.m8n8.x2.shared.b16 {%0,%1}, [%2];" \
        : "=r"((r)[0]), "=r"((r)[1]) : "r"(a))
#define MMA(c, a, b) \
    asm volatile("mma.sync.aligned.m16n8k16.row.col.f32.bf16.bf16.f32 " \
        "{%0,%1,%2,%3}, {%4,%5,%6,%7}, {%8,%9}, {%0,%1,%2,%3};" \
        : "+f"((c)[0]), "+f"((c)[1]), "+f"((c)[2]), "+f"((c)[3]) \
        : "r"((a)[0]), "r"((a)[1]), "r"((a)[2]), "r"((a)[3]), "r"((b)[0]), "r"((b)[1]))

// smem layout: 4 stages x (Ahi|Alo|Bhi|Blo), each 128 rows x 80B = 10240B
#define STG_BYTES 40960
#define SMEM_BIAS (4 * STG_BYTES)
#define SMEM_BYTES (SMEM_BIAS + 512)

// ---------------- small kernels ----------------
__global__ void zero_small() {
    int i = threadIdx.x;
    if (i < EE) { g_cnt[i] = 0; g_me[i] = 0.f; g_ce[i] = 0.f; }
}
__global__ void offsets_kernel() {
    if (threadIdx.x == 0) {
        int o = 0;
        for (int e = 0; e < EE; e++) { g_off[e] = o; o += g_cnt[e]; }
    }
}
__global__ void laux_kernel(float* out, int pos) {
    if (threadIdx.x == 0) {
        float la = 0.f;
        for (int e = 0; e < EE; e++)
            la += (g_me[e] / (float)TT) * (g_ce[e] / (float)TT) * (float)EE;
        out[pos] = la;
    }
}

// x -> bf16 hi/lo split
__global__ void xcvt(const float* __restrict__ x, bf16* __restrict__ xh,
                     bf16* __restrict__ xl, int n) {
    int i = blockIdx.x * blockDim.x + threadIdx.x;
    if (i < n) {
        float v = x[i];
        bf16 h = __float2bfloat16_rn(v);
        xh[i] = h;
        xl[i] = __float2bfloat16_rn(v - __bfloat162float(h));
    }
}

// W[K,N] fp32 -> Th[N,K], Tl[N,K] bf16 (transpose + split)
__global__ void transcvt(const float* __restrict__ W, bf16* __restrict__ Th,
                         bf16* __restrict__ Tl, int Kd, int Nd) {
    __shared__ float t[32][33];
    size_t zo = (size_t)blockIdx.z * Kd * Nd;
    W += zo; Th += zo; Tl += zo;
    int k0 = blockIdx.y * 32, n0 = blockIdx.x * 32;
    int tx = threadIdx.x, ty = threadIdx.y;
    #pragma unroll
    for (int j = 0; j < 4; j++)
        t[ty + j * 8][tx] = W[(size_t)(k0 + ty + j * 8) * Nd + n0 + tx];
    __syncthreads();
    #pragma unroll
    for (int j = 0; j < 4; j++) {
        float v = t[tx][ty + j * 8];
        bf16 h = __float2bfloat16_rn(v);
        size_t o = (size_t)(n0 + ty + j * 8) * Kd + k0 + tx;
        Th[o] = h;
        Tl[o] = __float2bfloat16_rn(v - __bfloat162float(h));
    }
}

// ---------------- gating ----------------
__global__ void gating_kernel(const float* __restrict__ Wg,
                              const float* __restrict__ Wc,
                              const float* __restrict__ bc) {
    int t = blockIdx.x;
    const float* hr = g_h + (size_t)t * HH;
    float accg[8] = {0.f,0.f,0.f,0.f,0.f,0.f,0.f,0.f};
    float c0a = 0.f, c1a = 0.f;
    for (int k = threadIdx.x; k < HH; k += 128) {
        float xv = hr[k];
        const float* wg = Wg + k * EE;
        #pragma unroll
        for (int e = 0; e < 8; e++) accg[e] += xv * wg[e];
        c0a += xv * Wc[k * 2 + 0];
        c1a += xv * Wc[k * 2 + 1];
    }
    __shared__ float red[128];
    __shared__ float vals[10];
    for (int v = 0; v < 10; v++) {
        float xx = (v < 8) ? accg[v] : ((v == 8) ? c0a : c1a);
        red[threadIdx.x] = xx; __syncthreads();
        for (int s = 64; s > 0; s >>= 1) {
            if (threadIdx.x < s) red[threadIdx.x] += red[threadIdx.x + s];
            __syncthreads();
        }
        if (threadIdx.x == 0) vals[v] = red[0];
        __syncthreads();
    }
    if (threadIdx.x == 0) {
        float g[8], mx = -1e30f;
        #pragma unroll
        for (int e = 0; e < 8; e++) mx = fmaxf(mx, vals[e]);
        float s = 0.f;
        #pragma unroll
        for (int e = 0; e < 8; e++) { g[e] = expf(vals[e] - mx); s += g[e]; }
        float invs = 1.f / s;
        #pragma unroll
        for (int e = 0; e < 8; e++) g[e] *= invs;
        int i1 = 0;
        #pragma unroll
        for (int e = 1; e < 8; e++) if (g[e] > g[i1]) i1 = e;
        int i2 = (i1 == 0) ? 1 : 0;
        #pragma unroll
        for (int e = 0; e < 8; e++) if (e != i1 && g[e] > g[i2]) i2 = e;
        float v1 = g[i1], v2 = g[i2];
        float wn = 1.f / (v1 + v2 + 1e-9f);
        float cc0 = vals[8] + bc[0], cc1 = vals[9] + bc[1];
        float m2 = fmaxf(cc0, cc1);
        float e0 = expf(cc0 - m2), e1 = expf(cc1 - m2);
        float cs = 1.f / (e0 + e1);
        float c0 = e0 * cs, c1 = e1 * cs;
        g_c1[t] = c1;
        int s1 = atomicAdd(&g_cnt[i1], 1);
        g_idx[i1 * TT + s1] = t; g_w[i1 * TT + s1] = v1 * wn * c0;
        int s2 = atomicAdd(&g_cnt[i2], 1);
        g_idx[i2 * TT + s2] = t; g_w[i2 * TT + s2] = v2 * wn * c0;
        #pragma unroll
        for (int e = 0; e < 8; e++) atomicAdd(&g_me[e], g[e]);
        atomicAdd(&g_ce[i1], 1.0f);
    }
}

// ---------------- bf16 3-term mma.sync GEMM, 128x128 tile, k-chunk 32 ----------------
// MODE 0: dense A; out = relu(acc+bias) -> fp32 C + bf16 hi/lo       (backbone)
// MODE 1: dense A; out = (acc+bias)*rowscale -> fp32 C                (resid FFN2)
// MODE 2: gathered A (g_idx); out row g_off[e]+r; relu -> bf16 hi/lo  (expert FFN1)
// MODE 3: packed A (g_off[e]+r); atomicAdd C[token] += w*(acc+bias)   (expert FFN2)
// MODE 4: dense A; out row r; relu -> bf16 hi/lo                      (resid FFN1)
template <int MODE>
__global__ __launch_bounds__(256, 1)
void mgemm(const bf16* __restrict__ Ah, const bf16* __restrict__ Al,
           const bf16* __restrict__ Bh, const bf16* __restrict__ Bl,
           float* __restrict__ C, bf16* __restrict__ Ch, bf16* __restrict__ Cl,
           const float* __restrict__ bias, int M, int N, int Kd,
           const float* __restrict__ rowscale) {
    extern __shared__ char smem[];
    const int e = blockIdx.z;
    int Mloc = (MODE == 2 || MODE == 3) ? g_cnt[e] : M;
    const int m0 = blockIdx.y * 128;
    if (m0 >= Mloc) return;
    const int n0 = blockIdx.x * 128;
    const int tid = threadIdx.x, lane = tid & 31, wid = tid >> 5;
    const int wm = wid & 3, wn = wid >> 2;
    const uint32_t sb = s2u(smem);
    float* sBias = (float*)(smem + SMEM_BIAS);

    const bf16* Bhe = Bh + (size_t)e * N * Kd;
    const bf16* Ble = Bl + (size_t)e * N * Kd;
    const float* bp = bias + (size_t)e * N;
    if (tid < 128) sBias[tid] = bp[n0 + tid];

    // loader: thread -> row tid>>1, chunk pair (tid&1)*2 (16B chunks of 8 bf16)
    const int lrow = tid >> 1, lc2 = (tid & 1) * 2;
    const int ar = m0 + lrow;
    const bool av = ar < Mloc;
    size_t arow;
    if (MODE == 2)      arow = av ? (size_t)g_idx[e * TT + ar] : 0;
    else if (MODE == 3) arow = (size_t)(g_off[e] + (av ? ar : 0));
    else                arow = av ? (size_t)ar : 0;
    const bf16* gAh = Ah + arow * Kd + lc2 * 8;
    const bf16* gAl = Al + arow * Kd + lc2 * 8;
    const bf16* gBh = Bhe + (size_t)(n0 + lrow) * Kd + lc2 * 8;
    const bf16* gBl = Ble + (size_t)(n0 + lrow) * Kd + lc2 * 8;
    const uint32_t sm0 = sb + lrow * 80 + lc2 * 16;

    const int NC = Kd >> 5;

#define LOAD_STAGE(s) do {                                                  \
        uint32_t st = sm0 + ((s) & 3) * STG_BYTES;                          \
        int go = (s) * 32;                                                  \
        cpa16(st + 0,          gAh + go,     av);                           \
        cpa16(st + 16,         gAh + go + 8, av);                           \
        cpa16(st + 10240,      gAl + go,     av);                           \
        cpa16(st + 10240 + 16, gAl + go + 8, av);                           \
        cpa16(st + 20480,      gBh + go,     true);                         \
        cpa16(st + 20480 + 16, gBh + go + 8, true);                         \
        cpa16(st + 30720,      gBl + go,     true);                         \
        cpa16(st + 30720 + 16, gBl + go + 8, true);                         \
        CPCOMMIT();                                                         \
    } while (0)

    const int pre = NC < 3 ? NC : 3;
    for (int s = 0; s < pre; s++) LOAD_STAGE(s);

    float acc[2][8][4];
    #pragma unroll
    for (int mi = 0; mi < 2; mi++)
        #pragma unroll
        for (int nj = 0; nj < 8; nj++)
            #pragma unroll
            for (int q = 0; q < 4; q++) acc[mi][nj][q] = 0.f;

    // ldmatrix per-lane base offsets (80B row stride => conflict-free, 5r mod 8 permutes)
    const uint32_t a_off = (uint32_t)((wm * 32 + (lane & 7) + ((lane >> 3) & 1) * 8) * 80
                                      + ((lane >> 4) & 1) * 16);
    const int l15 = lane & 15;
    const uint32_t b_off = (uint32_t)((wn * 64 + (l15 & 7)) * 80 + ((l15 >> 3) & 1) * 16);

    for (int kc = 0; kc < NC; kc++) {
        if (kc + 3 <= NC) CPWAIT(2);
        else if (kc + 2 == NC) CPWAIT(1);
        else CPWAIT(0);
        __syncthreads();
        if (kc + 3 < NC) LOAD_STAGE(kc + 3);

        const uint32_t stc = (kc & 3) * STG_BYTES;
        const uint32_t bAh = sb + stc + a_off;
        const uint32_t bAl = bAh + 10240;
        const uint32_t bBh = sb + stc + 20480 + b_off;
        const uint32_t bBl = bBh + 10240;

        #pragma unroll
        for (int ks = 0; ks < 2; ks++) {
            uint32_t ah[2][4], al[2][4], bh[8][2], bl[8][2];
            #pragma unroll
            for (int mi = 0; mi < 2; mi++) {
                LDSM4(ah[mi], bAh + mi * 1280 + ks * 32);
                LDSM4(al[mi], bAl + mi * 1280 + ks * 32);
            }
            #pragma unroll
            for (int nj = 0; nj < 8; nj++) {
                LDSM2(bh[nj], bBh + nj * 640 + ks * 32);
                LDSM2(bl[nj], bBl + nj * 640 + ks * 32);
            }
            #pragma unroll
            for (int mi = 0; mi < 2; mi++)
                #pragma unroll
                for (int nj = 0; nj < 8; nj++) {
                    MMA(acc[mi][nj], ah[mi], bh[nj]);
                    MMA(acc[mi][nj], ah[mi], bl[nj]);
                    MMA(acc[mi][nj], al[mi], bh[nj]);
                }
        }
    }

    // epilogue
    #pragma unroll
    for (int mi = 0; mi < 2; mi++) {
        const int rb = m0 + wm * 32 + mi * 16 + (lane >> 2);
        #pragma unroll
        for (int half = 0; half < 2; half++) {
            const int r = rb + half * 8;
            if (r >= Mloc) continue;
            float sc = 1.f, wv = 0.f; int ttk = 0;
            if (MODE == 1) sc = rowscale[r];
            if (MODE == 3) { ttk = g_idx[e * TT + r]; wv = g_w[e * TT + r]; }
            const int orow = (MODE == 2) ? (g_off[e] + r) : r;
            #pragma unroll
            for (int nj = 0; nj < 8; nj++) {
                const int cl = wn * 64 + nj * 8 + (lane & 3) * 2;
                float v0 = acc[mi][nj][half * 2 + 0] + sBias[cl];
                float v1 = acc[mi][nj][half * 2 + 1] + sBias[cl + 1];
                const size_t o = (size_t)orow * N + n0 + cl;
                if (MODE == 0 || MODE == 2 || MODE == 4) {
                    v0 = fmaxf(v0, 0.f); v1 = fmaxf(v1, 0.f);
                    bf16 h0 = __float2bfloat16_rn(v0);
                    bf16 h1 = __float2bfloat16_rn(v1);
                    bf16 l0 = __float2bfloat16_rn(v0 - __bfloat162float(h0));
                    bf16 l1 = __float2bfloat16_rn(v1 - __bfloat162float(h1));
                    *(__nv_bfloat162*)(Ch + o) = __nv_bfloat162(h0, h1);
                    *(__nv_bfloat162*)(Cl + o) = __nv_bfloat162(l0, l1);
                    if (MODE == 0) *(float2*)(C + o) = make_float2(v0, v1);
                } else if (MODE == 1) {
                    *(float2*)(C + o) = make_float2(v0 * sc, v1 * sc);
                } else {  // MODE 3
                    float* crow = C + (size_t)ttk * N + n0 + cl;
                    atomicAdd(&crow[0], wv * v0);
                    atomicAdd(&crow[1], wv * v1);
                }
            }
        }
    }
#undef LOAD_STAGE
}

// ---------------- head ----------------
__global__ void head_kernel(const float* __restrict__ Wh,
                            const float* __restrict__ bh,
                            float* __restrict__ logits) {
    __shared__ float sWt[10 * 1024];
    for (int i = threadIdx.x; i < 10240; i += 256) {
        int k = i / 10, c = i % 10;
        sWt[c * 1024 + k] = Wh[i];
    }
    __syncthreads();
    int warp = threadIdx.x >> 5, lane = threadIdx.x & 31;
    int t = blockIdx.x * 8 + warp;
    const float* orow = g_out + (size_t)t * HH;
    float acc[10];
    #pragma unroll
    for (int c = 0; c < 10; c++) acc[c] = 0.f;
    for (int k = lane; k < HH; k += 32) {
        float xv = orow[k];
        #pragma unroll
        for (int c = 0; c < 10; c++) acc[c] += xv * sWt[c * 1024 + k];
    }
    #pragma unroll
    for (int c = 0; c < 10; c++) {
        #pragma unroll
        for (int s = 16; s > 0; s >>= 1)
            acc[c] += __shfl_down_sync(0xffffffffu, acc[c], s);
    }
    if (lane == 0) {
        #pragma unroll
        for (int c = 0; c < 10; c++) logits[t * 10 + c] = acc[c] + bh[c];
    }
}

// ---------------- launch ----------------
extern "C" void kernel_launch(void* const* d_in, const int* in_sizes, int n_in,
                              void* d_out, int out_size) {
    const float* x   = (const float*)d_in[0];
    const float* Wb  = (const float*)d_in[1];
    const float* bb  = (const float*)d_in[2];
    const float* Wg  = (const float*)d_in[3];
    const float* W1  = (const float*)d_in[4];
    const float* b1  = (const float*)d_in[5];
    const float* W2  = (const float*)d_in[6];
    const float* b2  = (const float*)d_in[7];
    const float* Wr1 = (const float*)d_in[8];
    const float* br1 = (const float*)d_in[9];
    const float* Wr2 = (const float*)d_in[10];
    const float* br2 = (const float*)d_in[11];
    const float* Wc  = (const float*)d_in[12];
    const float* bc  = (const float*)d_in[13];
    const float* Wh  = (const float*)d_in[14];
    const float* bh  = (const float*)d_in[15];
    float* out = (float*)d_out;

    float *ph, *pout, *pc1;
    bf16 *pxh, *pxl, *phh, *phl, *pmh, *pml, *pWh, *pWl;
    cudaGetSymbolAddress((void**)&ph,  g_h);
    cudaGetSymbolAddress((void**)&pout, g_out);
    cudaGetSymbolAddress((void**)&pc1, g_c1);
    cudaGetSymbolAddress((void**)&pxh, g_xh);
    cudaGetSymbolAddress((void**)&pxl, g_xl);
    cudaGetSymbolAddress((void**)&phh, g_hh);
    cudaGetSymbolAddress((void**)&phl, g_hl);
    cudaGetSymbolAddress((void**)&pmh, g_mh);
    cudaGetSymbolAddress((void**)&pml, g_ml);
    cudaGetSymbolAddress((void**)&pWh, g_Wh);
    cudaGetSymbolAddress((void**)&pWl, g_Wl);

    cudaFuncSetAttribute(mgemm<0>, cudaFuncAttributeMaxDynamicSharedMemorySize, SMEM_BYTES);
    cudaFuncSetAttribute(mgemm<1>, cudaFuncAttributeMaxDynamicSharedMemorySize, SMEM_BYTES);
    cudaFuncSetAttribute(mgemm<2>, cudaFuncAttributeMaxDynamicSharedMemorySize, SMEM_BYTES);
    cudaFuncSetAttribute(mgemm<3>, cudaFuncAttributeMaxDynamicSharedMemorySize, SMEM_BYTES);
    cudaFuncSetAttribute(mgemm<4>, cudaFuncAttributeMaxDynamicSharedMemorySize, SMEM_BYTES);

    // weight transpose + bf16 split
    dim3 tb(32, 8);
    transcvt<<<dim3(HH / 32, HH / 32, 1),   tb>>>(Wb,  pWh + OFF_WB,  pWl + OFF_WB,  HH,  HH);
    transcvt<<<dim3(DFF / 32, HH / 32, 1),  tb>>>(Wr1, pWh + OFF_WR1, pWl + OFF_WR1, HH,  DFF);
    transcvt<<<dim3(HH / 32, DFF / 32, 1),  tb>>>(Wr2, pWh + OFF_WR2, pWl + OFF_WR2, DFF, HH);
    transcvt<<<dim3(DFF / 32, HH / 32, EE), tb>>>(W1,  pWh + OFF_W1,  pWl + OFF_W1,  HH,  DFF);
    transcvt<<<dim3(HH / 32, DFF / 32, EE), tb>>>(W2,  pWh + OFF_W2,  pWl + OFF_W2,  DFF, HH);

    xcvt<<<(TT * HH) / 512, 512>>>(x, pxh, pxl, TT * HH);
    zero_small<<<1, 32>>>();

    // backbone: h = relu(x@Wb + bb) -> fp32 + bf16 split
    mgemm<0><<<dim3(HH / 128, TT / 128, 1), 256, SMEM_BYTES>>>(
        pxh, pxl, pWh + OFF_WB, pWl + OFF_WB, ph, phh, phl, bb, TT, HH, HH, nullptr);

    gating_kernel<<<TT, 128>>>(Wg, Wc, bc);
    offsets_kernel<<<1, 32>>>();
    laux_kernel<<<1, 32>>>(out, out_size - 1);

    // residual branch
    mgemm<4><<<dim3(DFF / 128, TT / 128, 1), 256, SMEM_BYTES>>>(
        phh, phl, pWh + OFF_WR1, pWl + OFF_WR1, nullptr, pmh, pml, br1, TT, DFF, HH, nullptr);
    mgemm<1><<<dim3(HH / 128, TT / 128, 1), 256, SMEM_BYTES>>>(
        pmh, pml, pWh + OFF_WR2, pWl + OFF_WR2, pout, nullptr, nullptr, br2, TT, HH, DFF, pc1);

    // expert branch (grouped sparse)
    mgemm<2><<<dim3(DFF / 128, TT / 128, EE), 256, SMEM_BYTES>>>(
        phh, phl, pWh + OFF_W1, pWl + OFF_W1, nullptr,
        pmh + (size_t)TT * DFF, pml + (size_t)TT * DFF, b1, TT, DFF, HH, nullptr);
    mgemm<3><<<dim3(HH / 128, TT / 128, EE), 256, SMEM_BYTES>>>(
        pmh + (size_t)TT * DFF, pml + (size_t)TT * DFF, pWh + OFF_W2, pWl + OFF_W2,
        pout, nullptr, nullptr, b2, TT, HH, DFF, nullptr);

    head_kernel<<<TT / 8, 256>>>(Wh, bh, out);
}

// round 5
// speedup vs baseline: 2.7700x; 1.3268x over previous
#include <cuda_runtime.h>
#include <cuda_fp16.h>
#include <math.h>
#include <stdint.h>

#define TT   4096
#define HH   1024
#define EE   8
#define DFF  4096

typedef __half fp16;

// ---------------- scratch (static device globals; no allocation) ----------------
__device__ float g_h[TT * HH];                 // fp32 backbone activations (gating)
__device__ fp16  g_hh[TT * HH];                // h split hi
__device__ fp16  g_hl[TT * HH];                // h split lo
__device__ fp16  g_xh[TT * HH];
__device__ fp16  g_xl[TT * HH];
__device__ fp16  g_mh[3 * TT * DFF];           // mid hi: rows [0,TT) resid, [TT,3TT) expert-packed
__device__ fp16  g_ml[3 * TT * DFF];           // mid lo
__device__ float g_out[TT * HH];
__device__ int   g_idx[EE * TT];
__device__ float g_w[EE * TT];
__device__ float g_c1[TT];
__device__ int   g_cnt[EE];
__device__ int   g_off[EE];
__device__ float g_me[EE];
__device__ float g_ce[EE];

// transposed weight arena: [N,K] K-major fp16 (hi). Lo only for Wb (backbone 3-term).
#define OFF_WB   0
#define OFF_WR1  (1024 * 1024)
#define OFF_WR2  (OFF_WR1 + 1024 * 4096)
#define OFF_W1   (OFF_WR2 + 4096 * 1024)
#define OFF_W2   (OFF_W1 + 8 * 1024 * 4096)
#define WT_TOTAL (OFF_W2 + 8 * 4096 * 1024)
__device__ fp16 g_Wh[WT_TOTAL];
__device__ fp16 g_Wl[1024 * 1024];             // Wb lo only

// ---------------- PTX helpers (sm_80-baseline only; NO 'a'-features) ----------------
__device__ __forceinline__ uint32_t s2u(const void* p) {
    uint32_t a;
    asm("{ .reg .u64 t; cvta.to.shared.u64 t, %1; cvt.u32.u64 %0, t; }" : "=r"(a) : "l"(p));
    return a;
}
__device__ __forceinline__ void cpa16(uint32_t s, const void* g, bool v) {
    asm volatile("cp.async.cg.shared.global [%0], [%1], 16, %2;"
                 :: "r"(s), "l"(g), "r"(v ? 16 : 0));
}
#define CPCOMMIT() asm volatile("cp.async.commit_group;")
#define CPWAIT(n)  asm volatile("cp.async.wait_group %0;" :: "n"(n))

#define LDSM4(r, a) \
    asm volatile("ldmatrix.sync.aligned.m8n8.x4.shared.b16 {%0,%1,%2,%3}, [%4];" \
        : "=r"((r)[0]), "=r"((r)[1]), "=r"((r)[2]), "=r"((r)[3]) : "r"(a))
// B stored [N,K] K-major: NON-trans x2 yields exactly the mma col-major B fragment
#define LDSM2(r, a) \
    asm volatile("ldmatrix.sync.aligned.m8n8.x2.shared.b16 {%0,%1}, [%2];" \
        : "=r"((r)[0]), "=r"((r)[1]) : "r"(a))
#define MMA(c, a, b) \
    asm volatile("mma.sync.aligned.m16n8k16.row.col.f32.f16.f16.f32 " \
        "{%0,%1,%2,%3}, {%4,%5,%6,%7}, {%8,%9}, {%0,%1,%2,%3};" \
        : "+f"((c)[0]), "+f"((c)[1]), "+f"((c)[2]), "+f"((c)[3]) \
        : "r"((a)[0]), "r"((a)[1]), "r"((a)[2]), "r"((a)[3]), "r"((b)[0]), "r"((b)[1]))

// smem: 4 stages x (Ahi|Alo|Bhi|[Blo]); sub-buffer = 128 rows x 80B = 10240B
#define SMEM_BIAS  163840
#define SMEM_BYTES (SMEM_BIAS + 512)

// ---------------- small kernels ----------------
__global__ void zero_small() {
    int i = threadIdx.x;
    if (i < EE) { g_cnt[i] = 0; g_me[i] = 0.f; g_ce[i] = 0.f; }
}
__global__ void offsets_kernel() {
    if (threadIdx.x == 0) {
        int o = 0;
        for (int e = 0; e < EE; e++) { g_off[e] = o; o += g_cnt[e]; }
    }
}
__global__ void laux_kernel(float* out, int pos) {
    if (threadIdx.x == 0) {
        float la = 0.f;
        for (int e = 0; e < EE; e++)
            la += (g_me[e] / (float)TT) * (g_ce[e] / (float)TT) * (float)EE;
        out[pos] = la;
    }
}

// x -> fp16 hi/lo split
__global__ void xcvt(const float* __restrict__ x, fp16* __restrict__ xh,
                     fp16* __restrict__ xl, int n) {
    int i = blockIdx.x * blockDim.x + threadIdx.x;
    if (i < n) {
        float v = x[i];
        fp16 h = __float2half_rn(v);
        xh[i] = h;
        xl[i] = __float2half_rn(v - __half2float(h));
    }
}

// W[K,N] fp32 -> Th[N,K] fp16 (+ optional Tl lo-split)
template <bool LO>
__global__ void transcvt(const float* __restrict__ W, fp16* __restrict__ Th,
                         fp16* __restrict__ Tl, int Kd, int Nd) {
    __shared__ float t[32][33];
    size_t zo = (size_t)blockIdx.z * Kd * Nd;
    W += zo; Th += zo; if (LO) Tl += zo;
    int k0 = blockIdx.y * 32, n0 = blockIdx.x * 32;
    int tx = threadIdx.x, ty = threadIdx.y;
    #pragma unroll
    for (int j = 0; j < 4; j++)
        t[ty + j * 8][tx] = W[(size_t)(k0 + ty + j * 8) * Nd + n0 + tx];
    __syncthreads();
    #pragma unroll
    for (int j = 0; j < 4; j++) {
        float v = t[tx][ty + j * 8];
        fp16 h = __float2half_rn(v);
        size_t o = (size_t)(n0 + ty + j * 8) * Kd + k0 + tx;
        Th[o] = h;
        if (LO) Tl[o] = __float2half_rn(v - __half2float(h));
    }
}

// ---------------- gating ----------------
__global__ void gating_kernel(const float* __restrict__ Wg,
                              const float* __restrict__ Wc,
                              const float* __restrict__ bc) {
    int t = blockIdx.x;
    const float* hr = g_h + (size_t)t * HH;
    float accg[8] = {0.f,0.f,0.f,0.f,0.f,0.f,0.f,0.f};
    float c0a = 0.f, c1a = 0.f;
    for (int k = threadIdx.x; k < HH; k += 128) {
        float xv = hr[k];
        const float* wg = Wg + k * EE;
        #pragma unroll
        for (int e = 0; e < 8; e++) accg[e] += xv * wg[e];
        c0a += xv * Wc[k * 2 + 0];
        c1a += xv * Wc[k * 2 + 1];
    }
    __shared__ float red[128];
    __shared__ float vals[10];
    for (int v = 0; v < 10; v++) {
        float xx = (v < 8) ? accg[v] : ((v == 8) ? c0a : c1a);
        red[threadIdx.x] = xx; __syncthreads();
        for (int s = 64; s > 0; s >>= 1) {
            if (threadIdx.x < s) red[threadIdx.x] += red[threadIdx.x + s];
            __syncthreads();
        }
        if (threadIdx.x == 0) vals[v] = red[0];
        __syncthreads();
    }
    if (threadIdx.x == 0) {
        float g[8], mx = -1e30f;
        #pragma unroll
        for (int e = 0; e < 8; e++) mx = fmaxf(mx, vals[e]);
        float s = 0.f;
        #pragma unroll
        for (int e = 0; e < 8; e++) { g[e] = expf(vals[e] - mx); s += g[e]; }
        float invs = 1.f / s;
        #pragma unroll
        for (int e = 0; e < 8; e++) g[e] *= invs;
        int i1 = 0;
        #pragma unroll
        for (int e = 1; e < 8; e++) if (g[e] > g[i1]) i1 = e;
        int i2 = (i1 == 0) ? 1 : 0;
        #pragma unroll
        for (int e = 0; e < 8; e++) if (e != i1 && g[e] > g[i2]) i2 = e;
        float v1 = g[i1], v2 = g[i2];
        float wn = 1.f / (v1 + v2 + 1e-9f);
        float cc0 = vals[8] + bc[0], cc1 = vals[9] + bc[1];
        float m2 = fmaxf(cc0, cc1);
        float e0 = expf(cc0 - m2), e1 = expf(cc1 - m2);
        float cs = 1.f / (e0 + e1);
        float c0 = e0 * cs, c1 = e1 * cs;
        g_c1[t] = c1;
        int s1 = atomicAdd(&g_cnt[i1], 1);
        g_idx[i1 * TT + s1] = t; g_w[i1 * TT + s1] = v1 * wn * c0;
        int s2 = atomicAdd(&g_cnt[i2], 1);
        g_idx[i2 * TT + s2] = t; g_w[i2 * TT + s2] = v2 * wn * c0;
        #pragma unroll
        for (int e = 0; e < 8; e++) atomicAdd(&g_me[e], g[e]);
        atomicAdd(&g_ce[i1], 1.0f);
    }
}

// ---------------- fp16 mma.sync GEMM, 128x128 tile, k-chunk 32 ----------------
// TERMS=3: d = ah*bh + ah*bl + al*bh  (backbone; full fp32-equivalent accuracy)
// TERMS=2: d = ah*bh + al*bh          (B single-rounded fp16; err ~3e-4 RMS)
// MODE 0: dense A; out = relu(acc+bias) -> fp32 C + fp16 hi/lo       (backbone)
// MODE 1: dense A; out = (acc+bias)*rowscale -> fp32 C                (resid FFN2)
// MODE 2: gathered A (g_idx); out row g_off[e]+r; relu -> fp16 hi/lo  (expert FFN1)
// MODE 3: packed A (g_off[e]+r); atomicAdd C[token] += w*(acc+bias)   (expert FFN2)
// MODE 4: dense A; out row r; relu -> fp16 hi/lo                      (resid FFN1)
template <int MODE, int TERMS>
__global__ __launch_bounds__(256, 1)
void mgemm(const fp16* __restrict__ Ah, const fp16* __restrict__ Al,
           const fp16* __restrict__ Bh, const fp16* __restrict__ Bl,
           float* __restrict__ C, fp16* __restrict__ Ch, fp16* __restrict__ Cl,
           const float* __restrict__ bias, int M, int N, int Kd,
           const float* __restrict__ rowscale) {
    extern __shared__ char smem[];
    const int STG = (TERMS == 3) ? 40960 : 30720;   // stage stride (3 or 4 sub-buffers)
    const int e = blockIdx.z;
    int Mloc = (MODE == 2 || MODE == 3) ? g_cnt[e] : M;
    const int m0 = blockIdx.y * 128;
    if (m0 >= Mloc) return;
    const int n0 = blockIdx.x * 128;
    const int tid = threadIdx.x, lane = tid & 31, wid = tid >> 5;
    const int wm = wid & 3, wn = wid >> 2;
    const uint32_t sb = s2u(smem);
    float* sBias = (float*)(smem + SMEM_BIAS);

    const fp16* Bhe = Bh + (size_t)e * N * Kd;
    const float* bp = bias + (size_t)e * N;
    if (tid < 128) sBias[tid] = bp[n0 + tid];

    // loader: thread -> row tid>>1, chunk pair (tid&1)*2 (16B chunks of 8 fp16)
    const int lrow = tid >> 1, lc2 = (tid & 1) * 2;
    const int ar = m0 + lrow;
    const bool av = ar < Mloc;
    size_t arow;
    if (MODE == 2)      arow = av ? (size_t)g_idx[e * TT + ar] : 0;
    else if (MODE == 3) arow = (size_t)(g_off[e] + (av ? ar : 0));
    else                arow = av ? (size_t)ar : 0;
    const fp16* gAh = Ah + arow * Kd + lc2 * 8;
    const fp16* gAl = Al + arow * Kd + lc2 * 8;
    const fp16* gBh = Bhe + (size_t)(n0 + lrow) * Kd + lc2 * 8;
    const fp16* gBl = (TERMS == 3) ? (Bl + (size_t)(n0 + lrow) * Kd + lc2 * 8) : nullptr;
    const uint32_t sm0 = sb + lrow * 80 + lc2 * 16;

    const int NC = Kd >> 5;

#define LOAD_STAGE(s) do {                                                  \
        uint32_t st = sm0 + ((s) & 3) * STG;                                \
        int go = (s) * 32;                                                  \
        cpa16(st + 0,          gAh + go,     av);                           \
        cpa16(st + 16,         gAh + go + 8, av);                           \
        cpa16(st + 10240,      gAl + go,     av);                           \
        cpa16(st + 10240 + 16, gAl + go + 8, av);                           \
        cpa16(st + 20480,      gBh + go,     true);                         \
        cpa16(st + 20480 + 16, gBh + go + 8, true);                         \
        if (TERMS == 3) {                                                   \
            cpa16(st + 30720,      gBl + go,     true);                     \
            cpa16(st + 30720 + 16, gBl + go + 8, true);                     \
        }                                                                   \
        CPCOMMIT();                                                         \
    } while (0)

    const int pre = NC < 3 ? NC : 3;
    for (int s = 0; s < pre; s++) LOAD_STAGE(s);

    float acc[2][8][4];
    #pragma unroll
    for (int mi = 0; mi < 2; mi++)
        #pragma unroll
        for (int nj = 0; nj < 8; nj++)
            #pragma unroll
            for (int q = 0; q < 4; q++) acc[mi][nj][q] = 0.f;

    // ldmatrix per-lane base offsets (80B row stride => conflict-free, 5r mod 8 permutes)
    const uint32_t a_off = (uint32_t)((wm * 32 + (lane & 7) + ((lane >> 3) & 1) * 8) * 80
                                      + ((lane >> 4) & 1) * 16);
    const int l15 = lane & 15;
    const uint32_t b_off = (uint32_t)((wn * 64 + (l15 & 7)) * 80 + ((l15 >> 3) & 1) * 16);

    for (int kc = 0; kc < NC; kc++) {
        if (kc + 3 <= NC) CPWAIT(2);
        else if (kc + 2 == NC) CPWAIT(1);
        else CPWAIT(0);
        __syncthreads();
        if (kc + 3 < NC) LOAD_STAGE(kc + 3);

        const uint32_t stc = (kc & 3) * STG;
        const uint32_t bAh = sb + stc + a_off;
        const uint32_t bAl = bAh + 10240;
        const uint32_t bBh = sb + stc + 20480 + b_off;
        const uint32_t bBl = bBh + 10240;

        #pragma unroll
        for (int ks = 0; ks < 2; ks++) {
            uint32_t ah[2][4], al[2][4], bh[8][2], bl[8][2];
            #pragma unroll
            for (int mi = 0; mi < 2; mi++) {
                LDSM4(ah[mi], bAh + mi * 1280 + ks * 32);
                LDSM4(al[mi], bAl + mi * 1280 + ks * 32);
            }
            #pragma unroll
            for (int nj = 0; nj < 8; nj++) {
                LDSM2(bh[nj], bBh + nj * 640 + ks * 32);
                if (TERMS == 3) LDSM2(bl[nj], bBl + nj * 640 + ks * 32);
            }
            #pragma unroll
            for (int mi = 0; mi < 2; mi++)
                #pragma unroll
                for (int nj = 0; nj < 8; nj++) {
                    MMA(acc[mi][nj], ah[mi], bh[nj]);
                    if (TERMS == 3) MMA(acc[mi][nj], ah[mi], bl[nj]);
                    MMA(acc[mi][nj], al[mi], bh[nj]);
                }
        }
    }

    // epilogue
    #pragma unroll
    for (int mi = 0; mi < 2; mi++) {
        const int rb = m0 + wm * 32 + mi * 16 + (lane >> 2);
        #pragma unroll
        for (int half = 0; half < 2; half++) {
            const int r = rb + half * 8;
            if (r >= Mloc) continue;
            float sc = 1.f, wv = 0.f; int ttk = 0;
            if (MODE == 1) sc = rowscale[r];
            if (MODE == 3) { ttk = g_idx[e * TT + r]; wv = g_w[e * TT + r]; }
            const int orow = (MODE == 2) ? (g_off[e] + r) : r;
            #pragma unroll
            for (int nj = 0; nj < 8; nj++) {
                const int cl = wn * 64 + nj * 8 + (lane & 3) * 2;
                float v0 = acc[mi][nj][half * 2 + 0] + sBias[cl];
                float v1 = acc[mi][nj][half * 2 + 1] + sBias[cl + 1];
                const size_t o = (size_t)orow * N + n0 + cl;
                if (MODE == 0 || MODE == 2 || MODE == 4) {
                    v0 = fmaxf(v0, 0.f); v1 = fmaxf(v1, 0.f);
                    fp16 h0 = __float2half_rn(v0);
                    fp16 h1 = __float2half_rn(v1);
                    fp16 l0 = __float2half_rn(v0 - __half2float(h0));
                    fp16 l1 = __float2half_rn(v1 - __half2float(h1));
                    *(__half2*)(Ch + o) = __half2(h0, h1);
                    *(__half2*)(Cl + o) = __half2(l0, l1);
                    if (MODE == 0) *(float2*)(C + o) = make_float2(v0, v1);
                } else if (MODE == 1) {
                    *(float2*)(C + o) = make_float2(v0 * sc, v1 * sc);
                } else {  // MODE 3
                    float* crow = C + (size_t)ttk * N + n0 + cl;
                    atomicAdd(&crow[0], wv * v0);
                    atomicAdd(&crow[1], wv * v1);
                }
            }
        }
    }
#undef LOAD_STAGE
}

// ---------------- head ----------------
__global__ void head_kernel(const float* __restrict__ Wh,
                            const float* __restrict__ bh,
                            float* __restrict__ logits) {
    __shared__ float sWt[10 * 1024];
    for (int i = threadIdx.x; i < 10240; i += 256) {
        int k = i / 10, c = i % 10;
        sWt[c * 1024 + k] = Wh[i];
    }
    __syncthreads();
    int warp = threadIdx.x >> 5, lane = threadIdx.x & 31;
    int t = blockIdx.x * 8 + warp;
    const float* orow = g_out + (size_t)t * HH;
    float acc[10];
    #pragma unroll
    for (int c = 0; c < 10; c++) acc[c] = 0.f;
    for (int k = lane; k < HH; k += 32) {
        float xv = orow[k];
        #pragma unroll
        for (int c = 0; c < 10; c++) acc[c] += xv * sWt[c * 1024 + k];
    }
    #pragma unroll
    for (int c = 0; c < 10; c++) {
        #pragma unroll
        for (int s = 16; s > 0; s >>= 1)
            acc[c] += __shfl_down_sync(0xffffffffu, acc[c], s);
    }
    if (lane == 0) {
        #pragma unroll
        for (int c = 0; c < 10; c++) logits[t * 10 + c] = acc[c] + bh[c];
    }
}

// ---------------- launch ----------------
extern "C" void kernel_launch(void* const* d_in, const int* in_sizes, int n_in,
                              void* d_out, int out_size) {
    const float* x   = (const float*)d_in[0];
    const float* Wb  = (const float*)d_in[1];
    const float* bb  = (const float*)d_in[2];
    const float* Wg  = (const float*)d_in[3];
    const float* W1  = (const float*)d_in[4];
    const float* b1  = (const float*)d_in[5];
    const float* W2  = (const float*)d_in[6];
    const float* b2  = (const float*)d_in[7];
    const float* Wr1 = (const float*)d_in[8];
    const float* br1 = (const float*)d_in[9];
    const float* Wr2 = (const float*)d_in[10];
    const float* br2 = (const float*)d_in[11];
    const float* Wc  = (const float*)d_in[12];
    const float* bc  = (const float*)d_in[13];
    const float* Wh  = (const float*)d_in[14];
    const float* bh  = (const float*)d_in[15];
    float* out = (float*)d_out;

    float *ph, *pout, *pc1;
    fp16 *pxh, *pxl, *phh, *phl, *pmh, *pml, *pWh, *pWl;
    cudaGetSymbolAddress((void**)&ph,  g_h);
    cudaGetSymbolAddress((void**)&pout, g_out);
    cudaGetSymbolAddress((void**)&pc1, g_c1);
    cudaGetSymbolAddress((void**)&pxh, g_xh);
    cudaGetSymbolAddress((void**)&pxl, g_xl);
    cudaGetSymbolAddress((void**)&phh, g_hh);
    cudaGetSymbolAddress((void**)&phl, g_hl);
    cudaGetSymbolAddress((void**)&pmh, g_mh);
    cudaGetSymbolAddress((void**)&pml, g_ml);
    cudaGetSymbolAddress((void**)&pWh, g_Wh);
    cudaGetSymbolAddress((void**)&pWl, g_Wl);

    cudaFuncSetAttribute(mgemm<0,3>, cudaFuncAttributeMaxDynamicSharedMemorySize, SMEM_BYTES);
    cudaFuncSetAttribute(mgemm<1,2>, cudaFuncAttributeMaxDynamicSharedMemorySize, SMEM_BYTES);
    cudaFuncSetAttribute(mgemm<2,2>, cudaFuncAttributeMaxDynamicSharedMemorySize, SMEM_BYTES);
    cudaFuncSetAttribute(mgemm<3,2>, cudaFuncAttributeMaxDynamicSharedMemorySize, SMEM_BYTES);
    cudaFuncSetAttribute(mgemm<4,2>, cudaFuncAttributeMaxDynamicSharedMemorySize, SMEM_BYTES);

    // weight transpose + fp16 convert (lo-split only for backbone Wb)
    dim3 tb(32, 8);
    transcvt<true ><<<dim3(HH / 32, HH / 32, 1),   tb>>>(Wb,  pWh + OFF_WB,  pWl, HH,  HH);
    transcvt<false><<<dim3(DFF / 32, HH / 32, 1),  tb>>>(Wr1, pWh + OFF_WR1, nullptr, HH,  DFF);
    transcvt<false><<<dim3(HH / 32, DFF / 32, 1),  tb>>>(Wr2, pWh + OFF_WR2, nullptr, DFF, HH);
    transcvt<false><<<dim3(DFF / 32, HH / 32, EE), tb>>>(W1,  pWh + OFF_W1,  nullptr, HH,  DFF);
    transcvt<false><<<dim3(HH / 32, DFF / 32, EE), tb>>>(W2,  pWh + OFF_W2,  nullptr, DFF, HH);

    xcvt<<<(TT * HH) / 512, 512>>>(x, pxh, pxl, TT * HH);
    zero_small<<<1, 32>>>();

    // backbone: h = relu(x@Wb + bb) -> fp32 + fp16 split   (3-term: gating-accurate)
    mgemm<0,3><<<dim3(HH / 128, TT / 128, 1), 256, SMEM_BYTES>>>(
        pxh, pxl, pWh + OFF_WB, pWl, ph, phh, phl, bb, TT, HH, HH, nullptr);

    gating_kernel<<<TT, 128>>>(Wg, Wc, bc);
    offsets_kernel<<<1, 32>>>();
    laux_kernel<<<1, 32>>>(out, out_size - 1);

    // residual branch (2-term)
    mgemm<4,2><<<dim3(DFF / 128, TT / 128, 1), 256, SMEM_BYTES>>>(
        phh, phl, pWh + OFF_WR1, nullptr, nullptr, pmh, pml, br1, TT, DFF, HH, nullptr);
    mgemm<1,2><<<dim3(HH / 128, TT / 128, 1), 256, SMEM_BYTES>>>(
        pmh, pml, pWh + OFF_WR2, nullptr, pout, nullptr, nullptr, br2, TT, HH, DFF, pc1);

    // expert branch (grouped sparse, 2-term)
    mgemm<2,2><<<dim3(DFF / 128, TT / 128, EE), 256, SMEM_BYTES>>>(
        phh, phl, pWh + OFF_W1, nullptr, nullptr,
        pmh + (size_t)TT * DFF, pml + (size_t)TT * DFF, b1, TT, DFF, HH, nullptr);
    mgemm<3,2><<<dim3(HH / 128, TT / 128, EE), 256, SMEM_BYTES>>>(
        pmh + (size_t)TT * DFF, pml + (size_t)TT * DFF, pWh + OFF_W2, nullptr,
        pout, nullptr, nullptr, b2, TT, HH, DFF, nullptr);

    head_kernel<<<TT / 8, 256>>>(Wh, bh, out);
}